// round 1
// baseline (speedup 1.0000x reference)
#include <cuda_runtime.h>

// Problem constants
#define B_ 256
#define H_ 512
#define C_ 64
#define NKNOTS 100
#define KTERMS 8

// GEMM tiling: 32x32 CTA tile, BK=32, 128 threads, 4x2 per-thread tile.
// Grid = (256/32) x (512/32) = 8 x 16 = 128 CTAs.
#define BM 32
#define BN 32
#define BK 32

// Scratch (device globals; no allocation allowed)
__device__ float g_x[B_ * C_];
__device__ float g_xdot[B_ * C_];
__device__ float g_relu[B_ * H_];
__device__ float g_drelu[B_ * H_];
__device__ float g_dtanh[B_ * H_];
__device__ float g_u[B_ * H_];
__device__ float g_curr[B_ * H_];
__device__ float g_hdot[B_ * H_];

// ---------------------------------------------------------------------------
// Kernel 1: cubic spline eval at scalar t for x and xdot.
// coeffs layout: [B][N-1][4][C]
// ---------------------------------------------------------------------------
__global__ void spline_kernel(const float* __restrict__ tptr,
                              const float* __restrict__ tobs,
                              const float* __restrict__ coeffs,
                              const float* __restrict__ dcoeffs) {
    __shared__ int s_idx;
    __shared__ float s_dt;
    if (threadIdx.x == 0) {
        float t = tptr[0];
        int cnt = 0;
        for (int i = 0; i < NKNOTS; i++) cnt += (tobs[i] <= t) ? 1 : 0;
        int idx = cnt - 1;                 // searchsorted(side='right') - 1
        idx = max(0, min(idx, NKNOTS - 2));
        s_idx = idx;
        s_dt = t - tobs[idx];
    }
    __syncthreads();
    int gid = blockIdx.x * blockDim.x + threadIdx.x;
    if (gid >= B_ * C_) return;
    int b = gid / C_;
    int c = gid % C_;
    float dt = s_dt;
    size_t base = ((size_t)(b * (NKNOTS - 1) + s_idx)) * 4 * C_ + c;

    float a0 = coeffs[base + 0 * C_];
    float a1 = coeffs[base + 1 * C_];
    float a2 = coeffs[base + 2 * C_];
    float a3 = coeffs[base + 3 * C_];
    g_x[gid] = a0 + dt * (a1 + dt * (a2 + dt * a3));

    a0 = dcoeffs[base + 0 * C_];
    a1 = dcoeffs[base + 1 * C_];
    a2 = dcoeffs[base + 2 * C_];
    a3 = dcoeffs[base + 3 * C_];
    g_xdot[gid] = a0 + dt * (a1 + dt * (a2 + dt * a3));
}

// ---------------------------------------------------------------------------
// Core NT GEMM tile loop: acc[4][2] += A_tile(BMxK) * W_tile(BNxK)^T
// A, W already offset to the CTA's block row. K must be a multiple of BK.
// ---------------------------------------------------------------------------
__device__ __forceinline__ void gemm_tile_loop(
    const float* __restrict__ A, const float* __restrict__ W, int K,
    float (*As)[BM + 4], float (*Bs)[BN + 4], int tid, float acc[4][2]) {
    const int lrow = tid >> 3;          // 0..15
    const int lk4  = (tid & 7) << 2;    // 0,4,...,28
    const int tm   = (tid >> 4) << 2;   // 0..28
    const int tn   = (tid & 15) << 1;   // 0..30

    float4 pa0 = *(const float4*)(A + (size_t)lrow * K + lk4);
    float4 pa1 = *(const float4*)(A + (size_t)(lrow + 16) * K + lk4);
    float4 pb0 = *(const float4*)(W + (size_t)lrow * K + lk4);
    float4 pb1 = *(const float4*)(W + (size_t)(lrow + 16) * K + lk4);

    const int NT = K / BK;
    for (int t = 0; t < NT; ++t) {
        As[lk4 + 0][lrow]      = pa0.x; As[lk4 + 1][lrow]      = pa0.y;
        As[lk4 + 2][lrow]      = pa0.z; As[lk4 + 3][lrow]      = pa0.w;
        As[lk4 + 0][lrow + 16] = pa1.x; As[lk4 + 1][lrow + 16] = pa1.y;
        As[lk4 + 2][lrow + 16] = pa1.z; As[lk4 + 3][lrow + 16] = pa1.w;
        Bs[lk4 + 0][lrow]      = pb0.x; Bs[lk4 + 1][lrow]      = pb0.y;
        Bs[lk4 + 2][lrow]      = pb0.z; Bs[lk4 + 3][lrow]      = pb0.w;
        Bs[lk4 + 0][lrow + 16] = pb1.x; Bs[lk4 + 1][lrow + 16] = pb1.y;
        Bs[lk4 + 2][lrow + 16] = pb1.z; Bs[lk4 + 3][lrow + 16] = pb1.w;
        __syncthreads();

        if (t + 1 < NT) {
            int ko = (t + 1) * BK + lk4;
            pa0 = *(const float4*)(A + (size_t)lrow * K + ko);
            pa1 = *(const float4*)(A + (size_t)(lrow + 16) * K + ko);
            pb0 = *(const float4*)(W + (size_t)lrow * K + ko);
            pb1 = *(const float4*)(W + (size_t)(lrow + 16) * K + ko);
        }

        float4 a_cur = *(const float4*)&As[0][tm];
        float2 b_cur = *(const float2*)&Bs[0][tn];
#pragma unroll
        for (int k = 0; k < BK; ++k) {
            float4 a_nxt;
            float2 b_nxt;
            if (k + 1 < BK) {
                a_nxt = *(const float4*)&As[k + 1][tm];
                b_nxt = *(const float2*)&Bs[k + 1][tn];
            }
            acc[0][0] = fmaf(a_cur.x, b_cur.x, acc[0][0]);
            acc[0][1] = fmaf(a_cur.x, b_cur.y, acc[0][1]);
            acc[1][0] = fmaf(a_cur.y, b_cur.x, acc[1][0]);
            acc[1][1] = fmaf(a_cur.y, b_cur.y, acc[1][1]);
            acc[2][0] = fmaf(a_cur.z, b_cur.x, acc[2][0]);
            acc[2][1] = fmaf(a_cur.z, b_cur.y, acc[2][1]);
            acc[3][0] = fmaf(a_cur.w, b_cur.x, acc[3][0]);
            acc[3][1] = fmaf(a_cur.w, b_cur.y, acc[3][1]);
            if (k + 1 < BK) { a_cur = a_nxt; b_cur = b_nxt; }
        }
        __syncthreads();
    }
}

// ---------------------------------------------------------------------------
// Kernel 2: l1 = x@wx^T + h@wh^T + b0 ; wxd = xdot@wx^T
// Writes: g_relu = relu(l1), g_drelu = sigmoid(l1), g_u = drelu * wxd
// ---------------------------------------------------------------------------
__global__ __launch_bounds__(128) void gemm_l1(const float* __restrict__ h,
                                               const float* __restrict__ wh,
                                               const float* __restrict__ wx,
                                               const float* __restrict__ b0) {
    __shared__ float As[BK][BM + 4];
    __shared__ float Bs[BK][BN + 4];
    __shared__ float Xs[BK][BM + 4];
    const int tid = threadIdx.x;
    const int bm = blockIdx.x * BM;
    const int bn = blockIdx.y * BN;

    float acc[4][2] = {};
    gemm_tile_loop(h + (size_t)bm * H_, wh + (size_t)bn * H_, H_, As, Bs, tid, acc);

    // wx phase (K = 64): acc += x@wx^T, accw += xdot@wx^T, shared wx tile
    float accw[4][2] = {};
    {
        const int lrow = tid >> 3;
        const int lk4  = (tid & 7) << 2;
        const int tm   = (tid >> 4) << 2;
        const int tn   = (tid & 15) << 1;
        const float* Ax = g_x + (size_t)bm * C_;
        const float* Ad = g_xdot + (size_t)bm * C_;
        const float* Wx = wx + (size_t)bn * C_;
        for (int t = 0; t < C_ / BK; ++t) {
            int ko = t * BK + lk4;
            float4 px0 = *(const float4*)(Ax + (size_t)lrow * C_ + ko);
            float4 px1 = *(const float4*)(Ax + (size_t)(lrow + 16) * C_ + ko);
            float4 pd0 = *(const float4*)(Ad + (size_t)lrow * C_ + ko);
            float4 pd1 = *(const float4*)(Ad + (size_t)(lrow + 16) * C_ + ko);
            float4 pw0 = *(const float4*)(Wx + (size_t)lrow * C_ + ko);
            float4 pw1 = *(const float4*)(Wx + (size_t)(lrow + 16) * C_ + ko);
            As[lk4 + 0][lrow]      = px0.x; As[lk4 + 1][lrow]      = px0.y;
            As[lk4 + 2][lrow]      = px0.z; As[lk4 + 3][lrow]      = px0.w;
            As[lk4 + 0][lrow + 16] = px1.x; As[lk4 + 1][lrow + 16] = px1.y;
            As[lk4 + 2][lrow + 16] = px1.z; As[lk4 + 3][lrow + 16] = px1.w;
            Xs[lk4 + 0][lrow]      = pd0.x; Xs[lk4 + 1][lrow]      = pd0.y;
            Xs[lk4 + 2][lrow]      = pd0.z; Xs[lk4 + 3][lrow]      = pd0.w;
            Xs[lk4 + 0][lrow + 16] = pd1.x; Xs[lk4 + 1][lrow + 16] = pd1.y;
            Xs[lk4 + 2][lrow + 16] = pd1.z; Xs[lk4 + 3][lrow + 16] = pd1.w;
            Bs[lk4 + 0][lrow]      = pw0.x; Bs[lk4 + 1][lrow]      = pw0.y;
            Bs[lk4 + 2][lrow]      = pw0.z; Bs[lk4 + 3][lrow]      = pw0.w;
            Bs[lk4 + 0][lrow + 16] = pw1.x; Bs[lk4 + 1][lrow + 16] = pw1.y;
            Bs[lk4 + 2][lrow + 16] = pw1.z; Bs[lk4 + 3][lrow + 16] = pw1.w;
            __syncthreads();
#pragma unroll
            for (int k = 0; k < BK; ++k) {
                float4 av = *(const float4*)&As[k][tm];
                float4 xv = *(const float4*)&Xs[k][tm];
                float2 bv = *(const float2*)&Bs[k][tn];
                acc[0][0] = fmaf(av.x, bv.x, acc[0][0]);
                acc[0][1] = fmaf(av.x, bv.y, acc[0][1]);
                acc[1][0] = fmaf(av.y, bv.x, acc[1][0]);
                acc[1][1] = fmaf(av.y, bv.y, acc[1][1]);
                acc[2][0] = fmaf(av.z, bv.x, acc[2][0]);
                acc[2][1] = fmaf(av.z, bv.y, acc[2][1]);
                acc[3][0] = fmaf(av.w, bv.x, acc[3][0]);
                acc[3][1] = fmaf(av.w, bv.y, acc[3][1]);
                accw[0][0] = fmaf(xv.x, bv.x, accw[0][0]);
                accw[0][1] = fmaf(xv.x, bv.y, accw[0][1]);
                accw[1][0] = fmaf(xv.y, bv.x, accw[1][0]);
                accw[1][1] = fmaf(xv.y, bv.y, accw[1][1]);
                accw[2][0] = fmaf(xv.z, bv.x, accw[2][0]);
                accw[2][1] = fmaf(xv.z, bv.y, accw[2][1]);
                accw[3][0] = fmaf(xv.w, bv.x, accw[3][0]);
                accw[3][1] = fmaf(xv.w, bv.y, accw[3][1]);
            }
            __syncthreads();
        }
    }

    const int tm = (tid >> 4) << 2;
    const int tn = (tid & 15) << 1;
#pragma unroll
    for (int i = 0; i < 4; ++i) {
#pragma unroll
        for (int j = 0; j < 2; ++j) {
            int row = bm + tm + i;
            int col = bn + tn + j;
            size_t o = (size_t)row * H_ + col;
            float l1 = acc[i][j] + b0[col];
            g_relu[o] = fmaxf(l1, 0.0f);
            float dr = 1.0f / (1.0f + expf(-l1));
            g_drelu[o] = dr;
            g_u[o] = dr * accw[i][j];   // u0 = drelu * (xdot @ wx^T)
        }
    }
}

// ---------------------------------------------------------------------------
// Generic NT GEMM (K = H_) with mode-selected input & epilogue:
//  mode 0: A=g_relu, W=wout -> dtanh = 1 - tanh(acc + b1)^2
//  mode 1: A=g_curr, W=wh   -> g_u = g_drelu * acc
//  mode 2: A=g_u,    W=wout -> v = dtanh*acc; g_curr=v; g_hdot=v        (first)
//  mode 3: A=g_u,    W=wout -> v = dtanh*acc; g_curr=v; g_hdot+=v       (mid)
//  mode 4: A=g_u,    W=wout -> v = dtanh*acc; out = g_hdot + v          (last)
// ---------------------------------------------------------------------------
__global__ __launch_bounds__(128) void gemm_nt(const float* __restrict__ W,
                                               const float* __restrict__ bias,
                                               float* __restrict__ out,
                                               int mode) {
    __shared__ float As[BK][BM + 4];
    __shared__ float Bs[BK][BN + 4];
    const int tid = threadIdx.x;
    const int bm = blockIdx.x * BM;
    const int bn = blockIdx.y * BN;

    const float* A = (mode == 0) ? g_relu : (mode == 1) ? g_curr : g_u;

    float acc[4][2] = {};
    gemm_tile_loop(A + (size_t)bm * H_, W + (size_t)bn * H_, H_, As, Bs, tid, acc);

    const int tm = (tid >> 4) << 2;
    const int tn = (tid & 15) << 1;
#pragma unroll
    for (int i = 0; i < 4; ++i) {
#pragma unroll
        for (int j = 0; j < 2; ++j) {
            int row = bm + tm + i;
            int col = bn + tn + j;
            size_t o = (size_t)row * H_ + col;
            float v = acc[i][j];
            if (mode == 0) {
                float th = tanhf(v + bias[col]);
                g_dtanh[o] = 1.0f - th * th;
            } else if (mode == 1) {
                g_u[o] = g_drelu[o] * v;
            } else {
                v *= g_dtanh[o];
                if (mode == 2) {
                    g_curr[o] = v;
                    g_hdot[o] = v;
                } else if (mode == 3) {
                    g_curr[o] = v;
                    g_hdot[o] = g_hdot[o] + v;
                } else {
                    out[o] = g_hdot[o] + v;
                }
            }
        }
    }
}

// ---------------------------------------------------------------------------
extern "C" void kernel_launch(void* const* d_in, const int* in_sizes, int n_in,
                              void* d_out, int out_size) {
    const float* t      = (const float*)d_in[0];
    const float* h      = (const float*)d_in[1];
    const float* coeffs = (const float*)d_in[2];
    const float* dcoeff = (const float*)d_in[3];
    const float* tobs   = (const float*)d_in[4];
    const float* wx     = (const float*)d_in[5];
    const float* wh     = (const float*)d_in[6];
    const float* wout   = (const float*)d_in[7];
    const float* b0     = (const float*)d_in[8];
    const float* b1     = (const float*)d_in[9];
    float* out = (float*)d_out;

    spline_kernel<<<(B_ * C_ + 255) / 256, 256>>>(t, tobs, coeffs, dcoeff);

    dim3 grid(B_ / BM, H_ / BN);  // 8 x 16 = 128 CTAs
    // l1 / relu / drelu / u0
    gemm_l1<<<grid, 128>>>(h, wh, wx, b0);
    // dtanh from z = relu@wout^T + b1
    gemm_nt<<<grid, 128>>>(wout, b1, out, 0);
    // curr0 = dtanh * (u0 @ wout^T); hdot = curr0
    gemm_nt<<<grid, 128>>>(wout, b1, out, 2);
    // 8 von-Neumann iterations: u = drelu*(curr@wh^T); curr = dtanh*(u@wout^T)
    for (int k = 0; k < KTERMS; ++k) {
        gemm_nt<<<grid, 128>>>(wh, b1, out, 1);
        gemm_nt<<<grid, 128>>>(wout, b1, out, (k == KTERMS - 1) ? 4 : 3);
    }
}